// round 6
// baseline (speedup 1.0000x reference)
#include <cuda_runtime.h>

// Problem constants
#define B_SZ   2
#define S_LEN  2048
#define D_MOD  1024
#define HEADS  16
#define DHEAD  64
#define MROWS  (B_SZ * S_LEN)                                 // 4096
#define OUT_ELEMS  ((long)MROWS * D_MOD)                      // 4194304
#define ATTN_ELEMS ((long)B_SZ * HEADS * S_LEN * S_LEN)       // 134217728

// Scratch (static __device__ arrays: allocation-free per harness rules)
__device__ float g_q[MROWS * D_MOD];
__device__ float g_k[MROWS * D_MOD];
__device__ float g_v[MROWS * D_MOD];
__device__ float g_ctx[MROWS * D_MOD];
__device__ float g_attn_scratch[ATTN_ELEMS];

// ---------------------------------------------------------------------------
// helpers
// ---------------------------------------------------------------------------
__device__ __forceinline__ unsigned f2tf(float f) {
    unsigned u;
    asm("cvt.rna.tf32.f32 %0, %1;" : "=r"(u) : "f"(f));
    return u;
}
__device__ __forceinline__ uint4 cvt4(float4 f) {
    return make_uint4(f2tf(f.x), f2tf(f.y), f2tf(f.z), f2tf(f.w));
}
__device__ __forceinline__ void mma8(float* d, const unsigned* a, unsigned b0, unsigned b1) {
    asm volatile(
        "mma.sync.aligned.m16n8k8.row.col.f32.tf32.tf32.f32 "
        "{%0,%1,%2,%3}, {%4,%5,%6,%7}, {%8,%9}, {%0,%1,%2,%3};\n"
        : "+f"(d[0]), "+f"(d[1]), "+f"(d[2]), "+f"(d[3])
        : "r"(a[0]), "r"(a[1]), "r"(a[2]), "r"(a[3]), "r"(b0), "r"(b1));
}

// ---------------------------------------------------------------------------
// proj_mma: C[m][n] = A[m][k] * W[n][k] + bias[n]   (GEMM-NT)  — proven R1/R2
// ---------------------------------------------------------------------------
__global__ __launch_bounds__(256, 2) void proj_mma(
    const float* __restrict__ A, const float* __restrict__ W,
    const float* __restrict__ bias, float* __restrict__ C)
{
    __shared__ unsigned As[128][36];
    __shared__ unsigned Ws[128][36];

    const int tid = threadIdx.x;
    const int wid = tid >> 5, lane = tid & 31;
    const int g = lane >> 2, c = lane & 3;
    const int wm = wid >> 2;
    const int wn = wid & 3;
    const int m0 = blockIdx.y * 128, n0 = blockIdx.x * 128;

    float acc[4][4][4] = {};

    for (int k0 = 0; k0 < D_MOD; k0 += 32) {
        #pragma unroll
        for (int i = 0; i < 4; i++) {
            int idx = tid + i * 256;
            int row = idx >> 3, c4 = (idx & 7) * 4;
            float4 fa = *(const float4*)&A[(long)(m0 + row) * D_MOD + k0 + c4];
            float4 fw = *(const float4*)&W[(long)(n0 + row) * D_MOD + k0 + c4];
            *(uint4*)&As[row][c4] = cvt4(fa);
            *(uint4*)&Ws[row][c4] = cvt4(fw);
        }
        __syncthreads();

        #pragma unroll
        for (int ks = 0; ks < 4; ks++) {
            int kk = ks * 8;
            unsigned af[4][4], bf[4][2];
            #pragma unroll
            for (int mt = 0; mt < 4; mt++) {
                int r = wm * 64 + mt * 16 + g;
                af[mt][0] = As[r][kk + c];     af[mt][1] = As[r + 8][kk + c];
                af[mt][2] = As[r][kk + c + 4]; af[mt][3] = As[r + 8][kk + c + 4];
            }
            #pragma unroll
            for (int nt = 0; nt < 4; nt++) {
                int n = wn * 32 + nt * 8 + g;
                bf[nt][0] = Ws[n][kk + c];
                bf[nt][1] = Ws[n][kk + c + 4];
            }
            #pragma unroll
            for (int mt = 0; mt < 4; mt++)
                #pragma unroll
                for (int nt = 0; nt < 4; nt++)
                    mma8(acc[mt][nt], af[mt], bf[nt][0], bf[nt][1]);
        }
        __syncthreads();
    }

    #pragma unroll
    for (int nt = 0; nt < 4; nt++) {
        int col = n0 + wn * 32 + nt * 8 + 2 * c;
        float b0 = bias[col], b1 = bias[col + 1];
        #pragma unroll
        for (int mt = 0; mt < 4; mt++) {
            int r0 = m0 + wm * 64 + mt * 16 + g;
            float2 v0 = {acc[mt][nt][0] + b0, acc[mt][nt][1] + b1};
            float2 v1 = {acc[mt][nt][2] + b0, acc[mt][nt][3] + b1};
            *(float2*)&C[(long)r0 * D_MOD + col]       = v0;
            *(float2*)&C[(long)(r0 + 8) * D_MOD + col] = v1;
        }
    }
}

// ---------------------------------------------------------------------------
// Fused attention (all-tf32). FIX vs R3: Qs/Ks row stride 36 -> 68
// (full DHEAD=64 columns are stored per row; 36 caused row overlap).
//   pass 1: S = QK^T tiles -> online row max / sumexp
//   pass 2: recompute S, P = exp(s-m)/l -> write attn; P routed through
//           warp-private smem tile; PV via tf32 mma (R1 av_mma pattern).
// Warp layout: 8 warps x 16 rows; each warp owns full 128-col S strip.
// ---------------------------------------------------------------------------
#define QS_OFF  0
#define KS_OFF  34816
#define VS_OFF  69632
#define PS_OFF  106496
#define MSK_OFF 124928
#define SMEM_BYTES 133120

__global__ __launch_bounds__(256) void fused_attn(
    const float* __restrict__ q, const float* __restrict__ k,
    const float* __restrict__ v, const int* __restrict__ mask,
    float* __restrict__ attn, float* __restrict__ ctx)
{
    extern __shared__ char sm[];
    unsigned (*Qs)[68] = (unsigned(*)[68])(sm + QS_OFF);   // [m][k] tf32, 64 cols
    unsigned (*Ks)[68] = (unsigned(*)[68])(sm + KS_OFF);   // [n][k] tf32, 64 cols
    unsigned (*Vs)[72] = (unsigned(*)[72])(sm + VS_OFF);   // [k][n] tf32, 64 cols
    unsigned (*Ps)[36] = (unsigned(*)[36])(sm + PS_OFF);   // [m][32 k-sub] tf32
    int* Msk = (int*)(sm + MSK_OFF);

    const int bh = blockIdx.y;
    const int b = bh >> 4, h = bh & 15;
    const float* qh = q + (long)b * S_LEN * D_MOD + h * DHEAD;
    const float* kh = k + (long)b * S_LEN * D_MOD + h * DHEAD;
    const float* vh = v + (long)b * S_LEN * D_MOD + h * DHEAD;
    float* attn_bh = attn + (long)bh * S_LEN * S_LEN;

    const int tid = threadIdx.x;
    const int wid = tid >> 5, lane = tid & 31;
    const int g = lane >> 2, c = lane & 3;
    const int m0 = blockIdx.x * 128;
    const int r = wid * 16 + g;        // warp-local rows r and r+8

    for (int j = tid; j < S_LEN; j += 256)
        Msk[j] = mask[b * S_LEN + j];

    // Q tile (persistent): 128 rows x 64 k
    #pragma unroll
    for (int i = 0; i < 8; i++) {
        int idx = tid + i * 256;
        int row = idx >> 4, c4 = (idx & 15) * 4;
        *(uint4*)&Qs[row][c4] = cvt4(*(const float4*)&qh[(long)(m0 + row) * D_MOD + c4]);
    }
    __syncthreads();

    float m_0 = -60000.f, m_1 = -60000.f, l_0 = 0.f, l_1 = 0.f;

    // ---------------- pass 1: stats ----------------
    for (int kt = 0; kt < 16; kt++) {
        __syncthreads();
        #pragma unroll
        for (int i = 0; i < 8; i++) {
            int idx = tid + i * 256;
            int row = idx >> 4, c4 = (idx & 15) * 4;
            *(uint4*)&Ks[row][c4] =
                cvt4(*(const float4*)&kh[(long)(kt * 128 + row) * D_MOD + c4]);
        }
        __syncthreads();

        float acc[16][4] = {};
        #pragma unroll
        for (int ks = 0; ks < 8; ks++) {
            int kk = ks * 8;
            unsigned af[4];
            af[0] = Qs[r][kk + c];     af[1] = Qs[r + 8][kk + c];
            af[2] = Qs[r][kk + c + 4]; af[3] = Qs[r + 8][kk + c + 4];
            #pragma unroll
            for (int nt = 0; nt < 16; nt++)
                mma8(acc[nt], af, Ks[nt * 8 + g][kk + c], Ks[nt * 8 + g][kk + c + 4]);
        }

        float t0 = -60000.f, t1 = -60000.f;
        #pragma unroll
        for (int nt = 0; nt < 16; nt++) {
            int col = kt * 128 + nt * 8 + 2 * c;
            bool z0 = (Msk[col] == 0), z1 = (Msk[col + 1] == 0);
            acc[nt][0] = z0 ? -1e9f : acc[nt][0] * 0.125f;
            acc[nt][1] = z1 ? -1e9f : acc[nt][1] * 0.125f;
            acc[nt][2] = z0 ? -1e9f : acc[nt][2] * 0.125f;
            acc[nt][3] = z1 ? -1e9f : acc[nt][3] * 0.125f;
            t0 = fmaxf(t0, fmaxf(acc[nt][0], acc[nt][1]));
            t1 = fmaxf(t1, fmaxf(acc[nt][2], acc[nt][3]));
        }
        t0 = fmaxf(t0, __shfl_xor_sync(0xffffffffu, t0, 1));
        t0 = fmaxf(t0, __shfl_xor_sync(0xffffffffu, t0, 2));
        t1 = fmaxf(t1, __shfl_xor_sync(0xffffffffu, t1, 1));
        t1 = fmaxf(t1, __shfl_xor_sync(0xffffffffu, t1, 2));

        float m0n = fmaxf(m_0, t0), m1n = fmaxf(m_1, t1);
        float s0 = 0.f, s1 = 0.f;
        #pragma unroll
        for (int nt = 0; nt < 16; nt++) {
            s0 += __expf(acc[nt][0] - m0n) + __expf(acc[nt][1] - m0n);
            s1 += __expf(acc[nt][2] - m1n) + __expf(acc[nt][3] - m1n);
        }
        s0 += __shfl_xor_sync(0xffffffffu, s0, 1);
        s0 += __shfl_xor_sync(0xffffffffu, s0, 2);
        s1 += __shfl_xor_sync(0xffffffffu, s1, 1);
        s1 += __shfl_xor_sync(0xffffffffu, s1, 2);

        l_0 = l_0 * __expf(m_0 - m0n) + s0;  m_0 = m0n;
        l_1 = l_1 * __expf(m_1 - m1n) + s1;  m_1 = m1n;
    }

    const float inv0 = 1.f / l_0, inv1 = 1.f / l_1;

    // ---------------- pass 2: P write + PV ----------------
    float accO[8][4] = {};

    for (int kt = 0; kt < 16; kt++) {
        __syncthreads();
        #pragma unroll
        for (int i = 0; i < 8; i++) {
            int idx = tid + i * 256;
            int row = idx >> 4, c4 = (idx & 15) * 4;
            *(uint4*)&Ks[row][c4] =
                cvt4(*(const float4*)&kh[(long)(kt * 128 + row) * D_MOD + c4]);
            *(uint4*)&Vs[row][c4] =
                cvt4(*(const float4*)&vh[(long)(kt * 128 + row) * D_MOD + c4]);
        }
        __syncthreads();

        float acc[16][4] = {};
        #pragma unroll
        for (int ks = 0; ks < 8; ks++) {
            int kk = ks * 8;
            unsigned af[4];
            af[0] = Qs[r][kk + c];     af[1] = Qs[r + 8][kk + c];
            af[2] = Qs[r][kk + c + 4]; af[3] = Qs[r + 8][kk + c + 4];
            #pragma unroll
            for (int nt = 0; nt < 16; nt++)
                mma8(acc[nt], af, Ks[nt * 8 + g][kk + c], Ks[nt * 8 + g][kk + c + 4]);
        }

        // 4 sub-chunks of 32 columns: P -> gmem + warp-private smem, then PV
        #pragma unroll
        for (int sc = 0; sc < 4; sc++) {
            #pragma unroll
            for (int t = 0; t < 4; t++) {
                int nt = sc * 4 + t;
                int col = kt * 128 + nt * 8 + 2 * c;
                bool z0 = (Msk[col] == 0), z1 = (Msk[col + 1] == 0);
                float s0 = z0 ? -1e9f : acc[nt][0] * 0.125f;
                float s1 = z1 ? -1e9f : acc[nt][1] * 0.125f;
                float s2 = z0 ? -1e9f : acc[nt][2] * 0.125f;
                float s3 = z1 ? -1e9f : acc[nt][3] * 0.125f;
                float p0 = __expf(s0 - m_0) * inv0;
                float p1 = __expf(s1 - m_0) * inv0;
                float p2 = __expf(s2 - m_1) * inv1;
                float p3 = __expf(s3 - m_1) * inv1;
                long row0 = (long)(m0 + r) * S_LEN + col;
                *(float2*)&attn_bh[row0]              = make_float2(p0, p1);
                *(float2*)&attn_bh[row0 + 8L * S_LEN] = make_float2(p2, p3);
                int lc = t * 8 + 2 * c;
                Ps[r][lc]         = f2tf(p0);
                Ps[r][lc + 1]     = f2tf(p1);
                Ps[r + 8][lc]     = f2tf(p2);
                Ps[r + 8][lc + 1] = f2tf(p3);
            }
            __syncwarp();
            #pragma unroll
            for (int ks = 0; ks < 4; ks++) {
                int kk = ks * 8;
                unsigned af[4];
                af[0] = Ps[r][kk + c];     af[1] = Ps[r + 8][kk + c];
                af[2] = Ps[r][kk + c + 4]; af[3] = Ps[r + 8][kk + c + 4];
                int kv = sc * 32 + kk;
                #pragma unroll
                for (int on = 0; on < 8; on++)
                    mma8(accO[on], af, Vs[kv + c][on * 8 + g], Vs[kv + c + 4][on * 8 + g]);
            }
            __syncwarp();
        }
    }

    // epilogue: ctx in merged (row, h*64+col) layout
    float* op = ctx + ((long)b * S_LEN + m0 + r) * D_MOD + h * DHEAD;
    #pragma unroll
    for (int on = 0; on < 8; on++) {
        int col = on * 8 + 2 * c;
        *(float2*)&op[col]              = make_float2(accO[on][0], accO[on][1]);
        *(float2*)&op[8L * D_MOD + col] = make_float2(accO[on][2], accO[on][3]);
    }
}

// ---------------------------------------------------------------------------
extern "C" void kernel_launch(void* const* d_in, const int* in_sizes, int n_in,
                              void* d_out, int out_size)
{
    const float* Q    = (const float*)d_in[0];
    const float* K    = (const float*)d_in[1];
    const float* V    = (const float*)d_in[2];
    const int*   mask = (const int*)  d_in[3];
    const float* Wq   = (const float*)d_in[4];
    const float* bq   = (const float*)d_in[5];
    const float* Wk   = (const float*)d_in[6];
    const float* bk   = (const float*)d_in[7];
    const float* Wv   = (const float*)d_in[8];
    const float* bv   = (const float*)d_in[9];
    const float* Wo   = (const float*)d_in[10];
    const float* bo   = (const float*)d_in[11];

    float* out = (float*)d_out;

    float *q_p, *k_p, *v_p, *ctx_p, *attn_scr;
    cudaGetSymbolAddress((void**)&q_p,      g_q);
    cudaGetSymbolAddress((void**)&k_p,      g_k);
    cudaGetSymbolAddress((void**)&v_p,      g_v);
    cudaGetSymbolAddress((void**)&ctx_p,    g_ctx);
    cudaGetSymbolAddress((void**)&attn_scr, g_attn_scratch);

    float* attn = ((long)out_size >= OUT_ELEMS + ATTN_ELEMS)
                      ? (out + OUT_ELEMS) : attn_scr;

    cudaFuncSetAttribute(fused_attn,
                         cudaFuncAttributeMaxDynamicSharedMemorySize, SMEM_BYTES);

    dim3 projGrid(D_MOD / 128, MROWS / 128);          // (8, 32)
    proj_mma<<<projGrid, 256>>>(Q, Wq, bq, q_p);
    proj_mma<<<projGrid, 256>>>(K, Wk, bk, k_p);
    proj_mma<<<projGrid, 256>>>(V, Wv, bv, v_p);

    dim3 attnGrid(S_LEN / 128, B_SZ * HEADS);         // (16, 32)
    fused_attn<<<attnGrid, 256, SMEM_BYTES>>>(q_p, k_p, v_p, mask, attn, ctx_p);

    proj_mma<<<projGrid, 256>>>(ctx_p, Wo, bo, out);
}